// round 14
// baseline (speedup 1.0000x reference)
#include <cuda_runtime.h>
#include <cuda_fp16.h>
#include <cstdint>

#define S_LEN   2048
#define HEADS   12
#define BATCH   4
#define NBH     (BATCH * HEADS)
#define BT      128
#define NQB     (S_LEN / BT)   // 16
#define LDH     72             // padded smem row (halves)
#define NTHREADS 256

#define OUT_ELEMS  6291456LL
#define W_ELEMS    201326592LL

// smem (bytes): Q(128xLDH) | K0 | K1 | V0 | V1 (each 64xLDH)
#define QTILE_B (128 * LDH * 2)
#define KTILE_B (64 * LDH * 2)
#define OFF_Q   0
#define OFF_K0  (QTILE_B)
#define OFF_K1  (QTILE_B + KTILE_B)
#define OFF_V0  (QTILE_B + 2 * KTILE_B)
#define OFF_V1  (QTILE_B + 3 * KTILE_B)
#define SMEM_BYTES (QTILE_B + 4 * KTILE_B)

// pre-processed fp16 operands
__device__ __half g_Qh[(size_t)NBH * S_LEN * 64];   // [head][s][d], x 0.125*log2(e)
__device__ __half g_Kt[(size_t)NBH * 64 * S_LEN];   // [head][d][s]  (transposed)
__device__ __half g_Vh[(size_t)NBH * S_LEN * 64];   // [head][s][d]

__device__ __forceinline__ uint32_t pack_h2(float lo, float hi) {
    uint32_t r;
    asm("cvt.rn.f16x2.f32 %0, %1, %2;\n" : "=r"(r) : "f"(hi), "f"(lo));
    return r;
}
__device__ __forceinline__ float ex2(float x) {
    float r;
    asm("ex2.approx.f32 %0, %1;" : "=f"(r) : "f"(x));
    return r;
}
__device__ __forceinline__ void mma_f16(float* d,
                                        uint32_t a0, uint32_t a1, uint32_t a2, uint32_t a3,
                                        uint32_t b0, uint32_t b1) {
    asm volatile(
        "mma.sync.aligned.m16n8k16.row.col.f32.f16.f16.f32 "
        "{%0,%1,%2,%3}, {%4,%5,%6,%7}, {%8,%9}, {%0,%1,%2,%3};\n"
        : "+f"(d[0]), "+f"(d[1]), "+f"(d[2]), "+f"(d[3])
        : "r"(a0), "r"(a1), "r"(a2), "r"(a3), "r"(b0), "r"(b1));
}
__device__ __forceinline__ void ldsm4(uint32_t& r0, uint32_t& r1, uint32_t& r2, uint32_t& r3,
                                      uint32_t addr) {
    asm volatile("ldmatrix.sync.aligned.m8n8.x4.shared.b16 {%0,%1,%2,%3}, [%4];\n"
                 : "=r"(r0), "=r"(r1), "=r"(r2), "=r"(r3) : "r"(addr));
}
__device__ __forceinline__ void ldsm4t(uint32_t& r0, uint32_t& r1, uint32_t& r2, uint32_t& r3,
                                       uint32_t addr) {
    asm volatile("ldmatrix.sync.aligned.m8n8.x4.trans.shared.b16 {%0,%1,%2,%3}, [%4];\n"
                 : "=r"(r0), "=r"(r1), "=r"(r2), "=r"(r3) : "r"(addr));
}
__device__ __forceinline__ void cpa(uint32_t dst, const void* src) {
    asm volatile("cp.async.cg.shared.global [%0], [%1], 16;\n" :: "r"(dst), "l"(src));
}
#define CP_COMMIT() asm volatile("cp.async.commit_group;" ::: "memory")
#define CP_WAIT(n)  asm volatile("cp.async.wait_group %0;" :: "n"(n) : "memory")

// Q scale: 0.125 * log2(e)  (softmax done in exp2 domain)
#define QMULT 0.18033688011112042f

// ---------------- preprocess: split heads, fp16-convert, K transposed ----------------
__global__ void __launch_bounds__(256)
prep_kernel(const float* __restrict__ x) {
    __shared__ __half kt[64][LDH];
    const int bh = blockIdx.x, st = blockIdx.y;
    const int b = bh / HEADS, h = bh % HEADS;
    const float* xb = x + (size_t)b * S_LEN * 2304 + h * 64;
    const int s0 = st * 64;
    const int tid = threadIdx.x;

#pragma unroll
    for (int i = 0; i < 4; i++) {
        int idx = tid + i * 256;              // 0..1023
        int r = idx >> 4, c4 = (idx & 15) << 2;
        const float* row = xb + (size_t)(s0 + r) * 2304;
        float4 q = *reinterpret_cast<const float4*>(row + c4);
        float4 k = *reinterpret_cast<const float4*>(row + 768 + c4);
        float4 v = *reinterpret_cast<const float4*>(row + 1536 + c4);
        uint2 qp = make_uint2(pack_h2(q.x * QMULT, q.y * QMULT),
                              pack_h2(q.z * QMULT, q.w * QMULT));
        uint2 vp = make_uint2(pack_h2(v.x, v.y), pack_h2(v.z, v.w));
        *reinterpret_cast<uint2*>(g_Qh + ((size_t)bh * S_LEN + s0 + r) * 64 + c4) = qp;
        *reinterpret_cast<uint2*>(g_Vh + ((size_t)bh * S_LEN + s0 + r) * 64 + c4) = vp;
        uint2 kp = make_uint2(pack_h2(k.x, k.y), pack_h2(k.z, k.w));
        *reinterpret_cast<uint2*>(&kt[r][c4]) = kp;
    }
    __syncthreads();
#pragma unroll
    for (int i = 0; i < 2; i++) {
        int idx = tid + i * 256;              // 0..511
        int d = idx >> 3, c8 = (idx & 7) << 3;
        __half tmp[8];
#pragma unroll
        for (int t = 0; t < 8; t++) tmp[t] = kt[c8 + t][d];
        *reinterpret_cast<uint4*>(g_Kt + ((size_t)bh * 64 + d) * S_LEN + s0 + c8) =
            *reinterpret_cast<uint4*>(tmp);
    }
}

// ---- async tile loaders ----
__device__ __forceinline__ void ldQ(uint32_t smbase, const __half* g) {
#pragma unroll
    for (int i = 0; i < 4; i++) {
        int idx = threadIdx.x + i * NTHREADS;  // 0..1023 chunks of 16B (128 rows)
        int r = idx >> 3, c8 = (idx & 7) << 3;
        cpa(smbase + (uint32_t)((r * LDH + c8) * 2), g + (size_t)r * 64 + c8);
    }
}
__device__ __forceinline__ void ldKt(uint32_t smbase, const __half* g) {
#pragma unroll
    for (int i = 0; i < 2; i++) {
        int idx = threadIdx.x + i * NTHREADS;  // 0..511 (64 rows; row stride S_LEN)
        int r = idx >> 3, c8 = (idx & 7) << 3;
        cpa(smbase + (uint32_t)((r * LDH + c8) * 2), g + (size_t)r * S_LEN + c8);
    }
}
__device__ __forceinline__ void ldV(uint32_t smbase, const __half* g) {
#pragma unroll
    for (int i = 0; i < 2; i++) {
        int idx = threadIdx.x + i * NTHREADS;  // 0..511 (64 rows; row stride 64)
        int r = idx >> 3, c8 = (idx & 7) << 3;
        cpa(smbase + (uint32_t)((r * LDH + c8) * 2), g + (size_t)r * 64 + c8);
    }
}

// ---------------- main attention kernel ----------------
__global__ void __launch_bounds__(NTHREADS)
attn_kernel(float* __restrict__ o_out, float* __restrict__ w_out) {
    extern __shared__ float smem[];
    const uint32_t shb = (uint32_t)__cvta_generic_to_shared(smem);
    const uint32_t shQ = shb + OFF_Q;
    const uint32_t shK[2] = {shb + OFF_K0, shb + OFF_K1};
    const uint32_t shV[2] = {shb + OFF_V0, shb + OFF_V1};

    const int bh  = blockIdx.x;
    const int qbx = blockIdx.y;

    const __half* Qhead = g_Qh + (size_t)bh * S_LEN * 64;
    const __half* Khead = g_Kt + (size_t)bh * 64 * S_LEN;
    const __half* Vhead = g_Vh + (size_t)bh * S_LEN * 64;

    const int tid  = threadIdx.x;
    const int w    = tid >> 5;    // 0..7, owns q-rows w*16..w*16+15
    const int lane = tid & 31;
    const int ry   = lane >> 2;
    const int tx   = lane & 3;

    const int rA  = (lane & 7) + (((lane >> 3) & 1) << 3);
    const int cA8 = ((lane >> 4) & 1) << 3;
    const uint32_t aQ = shQ + (uint32_t)(((w * 16 + rA) * LDH + cA8) * 2);
    const int mIdx = lane >> 3, lrow = lane & 7;
    const uint32_t tOff = (uint32_t)(((((mIdx & 1) << 3) + lrow) * LDH + ((mIdx >> 1) << 3)) * 2);

#pragma unroll 1
    for (int half_ = 0; half_ < 2; half_++) {
        const int qb = half_ ? (NQB - 1 - qbx) : qbx;
        const int q0 = qb * BT;
        const int jd = 2 * qb + 1;             // last 64-wide k-tile
        const int r_lo = q0 + w * 16 + ry;
        const int r_hi = r_lo + 8;

        ldQ(shQ, Qhead + (size_t)q0 * 64);
        CP_COMMIT(); CP_WAIT(0);
        __syncthreads();

        uint32_t qf[4][4];
#pragma unroll
        for (int ch = 0; ch < 4; ch++)
            ldsm4(qf[ch][0], qf[ch][1], qf[ch][2], qf[ch][3], aQ + ch * 32u);

        // ---------------- pass A: row sums of exp2(S) ----------------
        float l0 = 0.f, l1 = 0.f;
        ldKt(shK[0], Khead); CP_COMMIT();
        for (int j = 0; j <= jd; j++) {
            if (j < jd) { ldKt(shK[(j + 1) & 1], Khead + (j + 1) * 64); CP_COMMIT(); CP_WAIT(1); }
            else        { CP_WAIT(0); }
            __syncthreads();
            const uint32_t kb = shK[j & 1] + tOff;

            float s[8][4];
#pragma unroll
            for (int nt = 0; nt < 8; nt++)
                s[nt][0] = s[nt][1] = s[nt][2] = s[nt][3] = 0.f;
#pragma unroll
            for (int ch = 0; ch < 4; ch++) {
#pragma unroll
                for (int ntp = 0; ntp < 4; ntp++) {
                    uint32_t b0, b1, b2, b3;
                    ldsm4t(b0, b1, b2, b3, kb + (uint32_t)((ch * 16 * LDH + ntp * 16) * 2));
                    mma_f16(s[2 * ntp],     qf[ch][0], qf[ch][1], qf[ch][2], qf[ch][3], b0, b1);
                    mma_f16(s[2 * ntp + 1], qf[ch][0], qf[ch][1], qf[ch][2], qf[ch][3], b2, b3);
                }
            }
            if (j >= jd - 1) {   // only the two diagonal-intersecting tiles need masking
#pragma unroll
                for (int nt = 0; nt < 8; nt++) {
#pragma unroll
                    for (int c = 0; c < 2; c++) {
                        int col = j * 64 + nt * 8 + tx * 2 + c;
                        if (col > r_lo) s[nt][c]     = -1e30f;
                        if (col > r_hi) s[nt][2 + c] = -1e30f;
                    }
                }
            }
#pragma unroll
            for (int nt = 0; nt < 8; nt++) {
                l0 += ex2(s[nt][0]) + ex2(s[nt][1]);
                l1 += ex2(s[nt][2]) + ex2(s[nt][3]);
            }
            __syncthreads();
        }
        l0 += __shfl_xor_sync(0xffffffffu, l0, 1);
        l0 += __shfl_xor_sync(0xffffffffu, l0, 2);
        l1 += __shfl_xor_sync(0xffffffffu, l1, 1);
        l1 += __shfl_xor_sync(0xffffffffu, l1, 2);
        const float inv0 = 1.0f / l0;
        const float inv1 = 1.0f / l1;

        float o[8][4];
#pragma unroll
        for (int nt = 0; nt < 8; nt++)
            o[nt][0] = o[nt][1] = o[nt][2] = o[nt][3] = 0.f;

        // ---------------- pass B: recompute, write W, PV ----------------
        ldKt(shK[0], Khead);
        ldV(shV[0], Vhead);
        CP_COMMIT();
        for (int j = 0; j <= jd; j++) {
            if (j < jd) {
                ldKt(shK[(j + 1) & 1], Khead + (j + 1) * 64);
                ldV(shV[(j + 1) & 1], Vhead + (size_t)(j + 1) * 64 * 64);
                CP_COMMIT(); CP_WAIT(1);
            } else { CP_WAIT(0); }
            __syncthreads();
            const uint32_t kb = shK[j & 1] + tOff;
            const uint32_t vb = shV[j & 1] + tOff;

            float s[8][4];
#pragma unroll
            for (int nt = 0; nt < 8; nt++)
                s[nt][0] = s[nt][1] = s[nt][2] = s[nt][3] = 0.f;
#pragma unroll
            for (int ch = 0; ch < 4; ch++) {
#pragma unroll
                for (int ntp = 0; ntp < 4; ntp++) {
                    uint32_t b0, b1, b2, b3;
                    ldsm4t(b0, b1, b2, b3, kb + (uint32_t)((ch * 16 * LDH + ntp * 16) * 2));
                    mma_f16(s[2 * ntp],     qf[ch][0], qf[ch][1], qf[ch][2], qf[ch][3], b0, b1);
                    mma_f16(s[2 * ntp + 1], qf[ch][0], qf[ch][1], qf[ch][2], qf[ch][3], b2, b3);
                }
            }
            if (j >= jd - 1) {
#pragma unroll
                for (int nt = 0; nt < 8; nt++) {
#pragma unroll
                    for (int c = 0; c < 2; c++) {
                        int col = j * 64 + nt * 8 + tx * 2 + c;
                        if (col > r_lo) s[nt][c]     = -1e30f;
                        if (col > r_hi) s[nt][2 + c] = -1e30f;
                    }
                }
            }

            // normalize -> W (streamed from regs) + fp16 A-frags
            uint32_t pa[4][4];
            size_t wb0 = ((size_t)bh * S_LEN + r_lo) * S_LEN + (size_t)j * 64 + 2 * tx;
            size_t wb1 = ((size_t)bh * S_LEN + r_hi) * S_LEN + (size_t)j * 64 + 2 * tx;
#pragma unroll
            for (int nt = 0; nt < 8; nt++) {
                float p0 = ex2(s[nt][0]) * inv0;
                float p1 = ex2(s[nt][1]) * inv0;
                float p2 = ex2(s[nt][2]) * inv1;
                float p3 = ex2(s[nt][3]) * inv1;
                if (w_out) {
                    __stcs(reinterpret_cast<float2*>(w_out + wb0 + nt * 8), make_float2(p0, p1));
                    __stcs(reinterpret_cast<float2*>(w_out + wb1 + nt * 8), make_float2(p2, p3));
                }
                const int ch = nt >> 1;
                if ((nt & 1) == 0) {
                    pa[ch][0] = pack_h2(p0, p1);
                    pa[ch][1] = pack_h2(p2, p3);
                } else {
                    pa[ch][2] = pack_h2(p0, p1);
                    pa[ch][3] = pack_h2(p2, p3);
                }
            }

            // O += P @ V
#pragma unroll
            for (int ch = 0; ch < 4; ch++) {
#pragma unroll
                for (int ntp = 0; ntp < 4; ntp++) {
                    uint32_t b0, b1, b2, b3;
                    ldsm4t(b0, b1, b2, b3, vb + (uint32_t)((ch * 16 * LDH + ntp * 16) * 2));
                    mma_f16(o[2 * ntp],     pa[ch][0], pa[ch][1], pa[ch][2], pa[ch][3], b0, b1);
                    mma_f16(o[2 * ntp + 1], pa[ch][0], pa[ch][1], pa[ch][2], pa[ch][3], b2, b3);
                }
            }
            __syncthreads();
        }

        // zero-fill strictly-upper tiles of W
        if (w_out) {
            int col0 = q0 + BT;
            if (col0 < S_LEN) {
                int Wd4 = (S_LEN - col0) >> 2;
                size_t base = ((size_t)bh * S_LEN + q0) * S_LEN + col0;
                float4 z = make_float4(0.f, 0.f, 0.f, 0.f);
                for (int idx = tid; idx < BT * Wd4; idx += NTHREADS) {
                    int r = idx / Wd4;
                    int c = idx - r * Wd4;
                    __stcs(reinterpret_cast<float4*>(w_out + base + (size_t)r * S_LEN) + c, z);
                }
            }
        }

        // write attn_output
        if (o_out) {
            size_t ob = (size_t)bh * S_LEN * 64;
#pragma unroll
            for (int nt = 0; nt < 8; nt++) {
                *reinterpret_cast<float2*>(o_out + ob + (size_t)r_lo * 64 + nt * 8 + 2 * tx) =
                    make_float2(o[nt][0], o[nt][1]);
                *reinterpret_cast<float2*>(o_out + ob + (size_t)r_hi * 64 + nt * 8 + 2 * tx) =
                    make_float2(o[nt][2], o[nt][3]);
            }
        }
        __syncthreads();
    }
}

extern "C" void kernel_launch(void* const* d_in, const int* in_sizes, int n_in,
                              void* d_out, int out_size) {
    const float* x = (const float*)d_in[0];
    float* out = (float*)d_out;

    float* o_ptr = nullptr;
    float* w_ptr = nullptr;
    if ((long long)out_size == OUT_ELEMS + W_ELEMS) { o_ptr = out; w_ptr = out + OUT_ELEMS; }
    else if ((long long)out_size == W_ELEMS)        { w_ptr = out; }
    else                                            { o_ptr = out; }

    dim3 pgrid(NBH, 32);
    prep_kernel<<<pgrid, 256>>>(x);

    cudaFuncSetAttribute(attn_kernel, cudaFuncAttributeMaxDynamicSharedMemorySize, SMEM_BYTES);
    dim3 grid(NBH, NQB / 2);
    attn_kernel<<<grid, NTHREADS, SMEM_BYTES>>>(o_ptr, w_ptr);
}